// round 7
// baseline (speedup 1.0000x reference)
#include <cuda_runtime.h>
#include <cuda_bf16.h>
#include <cstdint>

// ---------------- problem constants ----------------
#define BATCH   4
#define CIN     128
#define COUT    128
#define HDIM    128
#define WDIM    128
#define HW      (HDIM * WDIM)      // 16384
#define NGROUP  4
#define CG      32
#define KTAPS   9
#define RTOT    (CIN * KTAPS)      // 1152 = 72 * 16
#define NSTEP   72                 // global k16 steps
#define TPX     32                 // pixels (N) per block
#define NTHREADS 256

#define CHUNK_ROWS   144           // 16 cg x 9 taps = 9 k16 steps
#define NCHUNKS      8
#define STEPS_PER_CHUNK 9

// ---------------- smem layout (bytes) ----------------
// ring of 2 chunk buffers, each: hi [144][64B swizzled] = 9216, lo = 9216
#define SBUF_STRIDE  18432
#define SBUF_LO      9216
#define SMEM_MISC    (2 * SBUF_STRIDE)       // 36864
#define OFF_SS0      (SMEM_MISC + 0)
#define OFF_SS1      (SMEM_MISC + 128)
#define OFF_SWO      (SMEM_MISC + 256)
#define SMEM_BYTES   (SMEM_MISC + 832)       // 37696

// Weights pre-packed in m16n8k16 A-fragment order:
// b32 idx = (((step*8 + otile)*2 + plane)*32 + lane)*4 + q ; plane0=hi, plane1=lo
__device__ __align__(16) uint32_t g_wAf32[NSTEP * 8 * 2 * 32 * 4];   // 589824 B

__device__ __forceinline__ uint32_t smem_to_u32(const void* p) {
    uint32_t a;
    asm("{ .reg .u64 t; cvta.to.shared.u64 t, %1; cvt.u32.u64 %0, t; }" : "=r"(a) : "l"(p));
    return a;
}

// swizzle for 64B rows (32 px bf16): 4 x 16B chunks, chunk ^= (kk>>1)&3
__device__ __forceinline__ int s_off(int kk, int px) {
    return (kk << 6) + ((px & 7) << 1) + ((((px >> 3) ^ ((kk >> 1) & 3))) << 4);
}

__device__ __forceinline__ void ldsm_x4_trans(uint32_t* r, uint32_t addr) {
    asm volatile("ldmatrix.sync.aligned.m8n8.x4.trans.shared.b16 {%0,%1,%2,%3}, [%4];"
                 : "=r"(r[0]), "=r"(r[1]), "=r"(r[2]), "=r"(r[3]) : "r"(addr));
}
__device__ __forceinline__ void mma_bf16(float* c, const uint32_t* a, uint32_t b0, uint32_t b1) {
    asm volatile(
        "mma.sync.aligned.m16n8k16.row.col.f32.bf16.bf16.f32 "
        "{%0,%1,%2,%3}, {%4,%5,%6,%7}, {%8,%9}, {%0,%1,%2,%3};"
        : "+f"(c[0]), "+f"(c[1]), "+f"(c[2]), "+f"(c[3])
        : "r"(a[0]), "r"(a[1]), "r"(a[2]), "r"(a[3]), "r"(b0), "r"(b1));
}

__device__ __forceinline__ void bf16_split_store(char* hi_p, char* lo_p, float v) {
    __nv_bfloat16 h = __float2bfloat16(v);
    float hf = __bfloat162float(h);
    __nv_bfloat16 l = __float2bfloat16(v - hf);
    *(unsigned short*)hi_p = reinterpret_cast<unsigned short&>(h);
    *(unsigned short*)lo_p = reinterpret_cast<unsigned short&>(l);
}

// ---------------- prep: weights -> A-fragment layout, bf16 hi/lo ----------------
__global__ void prep_wAf_kernel(const float* __restrict__ wd) {
    int idx = blockIdx.x * 256 + threadIdx.x;       // b32 index
    if (idx >= NSTEP * 8 * 2 * 32 * 4) return;
    int q     = idx & 3;
    int lane  = (idx >> 2) & 31;
    int plane = (idx >> 7) & 1;
    int ot    = (idx >> 8) & 7;
    int step  = idx >> 11;
    int g = lane >> 2, t = lane & 3;
    int row = ot * 16 + g + ((q & 1) << 3);
    int col = step * 16 + t * 2 + ((q >> 1) << 3);
    float w0 = wd[row * RTOT + col];
    float w1 = wd[row * RTOT + col + 1];
    __nv_bfloat16 h0 = __float2bfloat16(w0);
    __nv_bfloat16 h1 = __float2bfloat16(w1);
    unsigned short u0, u1;
    if (plane == 0) {
        u0 = reinterpret_cast<unsigned short&>(h0);
        u1 = reinterpret_cast<unsigned short&>(h1);
    } else {
        __nv_bfloat16 l0 = __float2bfloat16(w0 - __bfloat162float(h0));
        __nv_bfloat16 l1 = __float2bfloat16(w1 - __bfloat162float(h1));
        u0 = reinterpret_cast<unsigned short&>(l0);
        u1 = reinterpret_cast<unsigned short&>(l1);
    }
    g_wAf32[idx] = ((uint32_t)u1 << 16) | (uint32_t)u0;
}

// ---------------- producer: sample one chunk (16 cg x 9 taps x 32 px) ----------
// chunk c: group g = c>>1, cg base = (c&1)*16; rows kk = (cg-cg0)*9 + tap
__device__ __forceinline__ void produce_chunk(
    char* sbuf, int c, int b, int h, int w0,
    const float* __restrict__ x, const float* ss0, const float* ss1,
    const float* swo, int ptid)
{
    const int g   = c >> 1;
    const int cg0 = (c & 1) << 4;
    const float* xb = x + ((size_t)b * CIN + g * CG + cg0) * HW;

    for (int i = ptid; i < KTAPS * TPX; i += 128) {
        int tap = i >> 5, px = i & 31;
        int ky = tap / 3, kx = tap - ky * 3;
        int gk = g * 9 + tap;
        float s0 = ss0[px], s1 = ss1[px];
        float offy = swo[gk*4 + 0] * s0 + swo[gk*4 + 1] * s1;
        float offx = swo[gk*4 + 2] * s0 + swo[gk*4 + 3] * s1;
        float py  = offy + (float)(ky - 1 + h);
        float pxf = offx + (float)(kx - 1 + w0 + px);
        float y0f = floorf(py), x0f = floorf(pxf);
        float fy = py - y0f, fx = pxf - x0f;
        int y0 = (int)y0f, x0 = (int)x0f;

        float aw[4]; int ai[4];
        #pragma unroll
        for (int t = 0; t < 4; t++) {
            int dy = t >> 1, dx = t & 1;
            int yi = y0 + dy, xi = x0 + dx;
            bool valid = (yi >= 0) && (yi < HDIM) && (xi >= 0) && (xi < WDIM);
            float wy = dy ? fy : 1.0f - fy;
            float wx = dx ? fx : 1.0f - fx;
            int yc = min(max(yi, 0), HDIM - 1);
            int xc = min(max(xi, 0), WDIM - 1);
            aw[t] = valid ? (wy * wx) : 0.0f;
            ai[t] = yc * WDIM + xc;
        }

        #pragma unroll 4
        for (int cg = 0; cg < 16; cg++) {
            const float* xc = xb + (size_t)cg * HW;
            float v = aw[0]*xc[ai[0]] + aw[1]*xc[ai[1]] + aw[2]*xc[ai[2]] + aw[3]*xc[ai[3]];
            int kk  = cg * KTAPS + tap;
            int off = s_off(kk, px);
            bf16_split_store(sbuf + off, sbuf + SBUF_LO + off, v);
        }
    }
}

// ---------------- main kernel ----------------
__global__ void __launch_bounds__(NTHREADS, 2)
deform_kernel(const float* __restrict__ x,        // [B,C,H,W]
              const float* __restrict__ shape,    // [B,2,H,W]
              const float* __restrict__ w_offset, // [72][2]
              float* __restrict__ out)            // [B,COUT,H,W]
{
    extern __shared__ char smem[];
    const uint32_t smem_u32 = smem_to_u32(smem);
    float* ss0 = (float*)(smem + OFF_SS0);
    float* ss1 = (float*)(smem + OFF_SS1);
    float* swo = (float*)(smem + OFF_SWO);

    const int tid = threadIdx.x;
    const int wid = tid >> 5;
    const int lid = tid & 31;

    const int b   = blockIdx.x >> 9;
    const int rem = blockIdx.x & 511;
    const int h   = rem >> 2;
    const int w0  = (rem & 3) << 5;

    // ---- stage small tables ----
    if (tid < 32)                     ss0[tid]     = shape[(size_t)(b*2+0)*HW + h*WDIM + w0 + tid];
    else if (tid < 64)                ss1[tid-32]  = shape[(size_t)(b*2+1)*HW + h*WDIM + w0 + (tid-32)];
    else if (tid >= 64 && tid < 208)  swo[tid-64]  = w_offset[tid-64];
    __syncthreads();

    const bool is_prod = (wid < 4);
    const int  cwid    = wid - 4;

    // consumer state
    const uint4* gA = reinterpret_cast<const uint4*>(g_wAf32);
    const int ot0   = cwid << 1;
    const int bkrow = lid & 15;
    const int bsel  = lid >> 4;

    float acc[2][4][4];
    uint4 curA[2][2];

    // ---- prologue: producers fill chunk 0; consumers preload A(step 0) ----
    if (is_prod) {
        produce_chunk(smem, 0, b, h, w0, x, ss0, ss1, swo, tid);
    } else {
        #pragma unroll
        for (int a1 = 0; a1 < 2; a1++)
            #pragma unroll
            for (int a2 = 0; a2 < 4; a2++)
                #pragma unroll
                for (int a3 = 0; a3 < 4; a3++) acc[a1][a2][a3] = 0.0f;
        #pragma unroll
        for (int ot = 0; ot < 2; ot++)
            #pragma unroll
            for (int pl = 0; pl < 2; pl++)
                curA[ot][pl] = gA[(((0*8 + ot0 + ot)*2 + pl) << 5) + lid];
    }
    __syncthreads();

    // ---- pipelined chunk loop ----
    for (int c = 0; c < NCHUNKS; c++) {
        if (is_prod) {
            if (c + 1 < NCHUNKS)
                produce_chunk(smem + ((c + 1) & 1) * SBUF_STRIDE, c + 1,
                              b, h, w0, x, ss0, ss1, swo, tid);
        } else {
            const uint32_t sb = smem_u32 + (uint32_t)((c & 1) * SBUF_STRIDE);
            #pragma unroll
            for (int s = 0; s < STEPS_PER_CHUNK; s++) {
                const int gs = c * STEPS_PER_CHUNK + s;
                // prefetch next step's A fragments
                uint4 nxtA[2][2];
                if (gs + 1 < NSTEP) {
                    #pragma unroll
                    for (int ot = 0; ot < 2; ot++)
                        #pragma unroll
                        for (int pl = 0; pl < 2; pl++)
                            nxtA[ot][pl] = gA[((((gs+1)*8 + ot0 + ot)*2 + pl) << 5) + lid];
                }

                // B fragments: hi/lo planes, two n16 halves
                const int kk = (s << 4) + bkrow;
                uint32_t bh[2][4], bl[2][4];
                #pragma unroll
                for (int half = 0; half < 2; half++) {
                    int bnchk = (half << 1) + bsel;
                    int boff  = (kk << 6) + (((bnchk ^ ((kk >> 1) & 3))) << 4);
                    ldsm_x4_trans(bh[half], sb + (uint32_t)boff);
                    ldsm_x4_trans(bl[half], sb + SBUF_LO + (uint32_t)boff);
                }

                // 24 MMAs
                #pragma unroll
                for (int ot = 0; ot < 2; ot++) {
                    const uint32_t* ah = (const uint32_t*)&curA[ot][0];
                    const uint32_t* al = (const uint32_t*)&curA[ot][1];
                    #pragma unroll
                    for (int half = 0; half < 2; half++) {
                        mma_bf16(acc[ot][half*2+0], ah, bh[half][0], bh[half][1]);
                        mma_bf16(acc[ot][half*2+1], ah, bh[half][2], bh[half][3]);
                        mma_bf16(acc[ot][half*2+0], ah, bl[half][0], bl[half][1]);
                        mma_bf16(acc[ot][half*2+1], ah, bl[half][2], bl[half][3]);
                        mma_bf16(acc[ot][half*2+0], al, bh[half][0], bh[half][1]);
                        mma_bf16(acc[ot][half*2+1], al, bh[half][2], bh[half][3]);
                    }
                }

                #pragma unroll
                for (int ot = 0; ot < 2; ot++)
                    #pragma unroll
                    for (int pl = 0; pl < 2; pl++)
                        curA[ot][pl] = nxtA[ot][pl];
            }
        }
        __syncthreads();
    }

    // ---- epilogue: consumers write o32 x 32px with ReLU ----
    if (is_prod) return;
    const int g = lid >> 2, t = lid & 3;
    #pragma unroll
    for (int ot = 0; ot < 2; ot++) {
        #pragma unroll
        for (int j = 0; j < 4; j++) {
            int o  = (cwid << 5) + (ot << 4) + g;
            int px = (j << 3) + (t << 1);
            float* op0 = out + (((size_t)b * COUT + o) << 14) + (h << 7) + w0 + px;
            float* op1 = op0 + ((size_t)8 << 14);   // row o+8
            float2 v0 = { fmaxf(acc[ot][j][0], 0.0f), fmaxf(acc[ot][j][1], 0.0f) };
            float2 v1 = { fmaxf(acc[ot][j][2], 0.0f), fmaxf(acc[ot][j][3], 0.0f) };
            *reinterpret_cast<float2*>(op0) = v0;
            *reinterpret_cast<float2*>(op1) = v1;
        }
    }
}

extern "C" void kernel_launch(void* const* d_in, const int* in_sizes, int n_in,
                              void* d_out, int out_size) {
    const float* x        = (const float*)d_in[0];
    const float* shape    = (const float*)d_in[1];
    const float* w_offset = (const float*)d_in[2];
    const float* w_deform = (const float*)d_in[3];
    float* out = (float*)d_out;

    cudaFuncSetAttribute(deform_kernel,
                         cudaFuncAttributeMaxDynamicSharedMemorySize, SMEM_BYTES);

    prep_wAf_kernel<<<(NSTEP * 8 * 2 * 32 * 4 + 255) / 256, 256>>>(w_deform);

    const int nblocks = BATCH * HDIM * (WDIM / TPX);   // 2048
    deform_kernel<<<nblocks, NTHREADS, SMEM_BYTES>>>(x, shape, w_offset, out);
}

// round 8
// speedup vs baseline: 1.6441x; 1.6441x over previous
#include <cuda_runtime.h>
#include <cuda_fp16.h>
#include <cstdint>

// ---------------- problem constants ----------------
#define BATCH   4
#define CIN     128
#define COUT    128
#define HDIM    128
#define WDIM    128
#define HW      (HDIM * WDIM)      // 16384
#define NGROUP  4
#define CG      32
#define KTAPS   9
#define RTOT    (CIN * KTAPS)      // 1152 = 72 * 16
#define NSTEP   72                 // k16 steps
#define TPX     32                 // pixels (N) per block
#define NTHREADS 256

// ---------------- smem layout (bytes) ----------------
// S (samples, f16 single plane): [1152 k][64 B swizzled row] = 73728
// misc @ 73728: ss0(128), ss1(128), swo(576)
#define SMEM_S_OFF   0
#define SMEM_MISC    73728
#define OFF_SS0      (SMEM_MISC + 0)
#define OFF_SS1      (SMEM_MISC + 128)
#define OFF_SWO      (SMEM_MISC + 256)
#define SMEM_BYTES   (SMEM_MISC + 832)   // 74560

// Weights pre-packed in m16n8k16 A-fragment order, f16 hi/lo planes:
// b32 idx = (((step*8 + otile)*2 + plane)*32 + lane)*4 + q
__device__ __align__(16) uint32_t g_wAf32[NSTEP * 8 * 2 * 32 * 4];   // 589824 B

__device__ __forceinline__ uint32_t smem_to_u32(const void* p) {
    uint32_t a;
    asm("{ .reg .u64 t; cvta.to.shared.u64 t, %1; cvt.u32.u64 %0, t; }" : "=r"(a) : "l"(p));
    return a;
}

// S swizzle: row k is 64B (32 px f16), 4 x 16B chunks; chunk ^= (k>>1)&3 so
// ldmatrix's 8-row phases hit disjoint 16B groups.
__device__ __forceinline__ int s_off(int k, int px) {
    return (k << 6) + ((px & 7) << 1) + ((((px >> 3) ^ ((k >> 1) & 3))) << 4);
}

__device__ __forceinline__ void ldsm_x4_trans(uint32_t* r, uint32_t addr) {
    asm volatile("ldmatrix.sync.aligned.m8n8.x4.trans.shared.b16 {%0,%1,%2,%3}, [%4];"
                 : "=r"(r[0]), "=r"(r[1]), "=r"(r[2]), "=r"(r[3]) : "r"(addr));
}
__device__ __forceinline__ void mma_f16(float* c, const uint32_t* a, uint32_t b0, uint32_t b1) {
    asm volatile(
        "mma.sync.aligned.m16n8k16.row.col.f32.f16.f16.f32 "
        "{%0,%1,%2,%3}, {%4,%5,%6,%7}, {%8,%9}, {%0,%1,%2,%3};"
        : "+f"(c[0]), "+f"(c[1]), "+f"(c[2]), "+f"(c[3])
        : "r"(a[0]), "r"(a[1]), "r"(a[2]), "r"(a[3]), "r"(b0), "r"(b1));
}

// ---------------- prep: weights -> A-fragment layout, f16 hi/lo ----------------
__global__ void prep_wAf_kernel(const float* __restrict__ wd) {
    int idx = blockIdx.x * 256 + threadIdx.x;       // b32 index
    if (idx >= NSTEP * 8 * 2 * 32 * 4) return;
    int q     = idx & 3;
    int lane  = (idx >> 2) & 31;
    int plane = (idx >> 7) & 1;
    int ot    = (idx >> 8) & 7;
    int step  = idx >> 11;
    int g = lane >> 2, t = lane & 3;
    int row = ot * 16 + g + ((q & 1) << 3);
    int col = step * 16 + t * 2 + ((q >> 1) << 3);
    float w0 = wd[row * RTOT + col];
    float w1 = wd[row * RTOT + col + 1];
    __half h0 = __float2half_rn(w0);
    __half h1 = __float2half_rn(w1);
    unsigned short u0, u1;
    if (plane == 0) {
        u0 = reinterpret_cast<unsigned short&>(h0);
        u1 = reinterpret_cast<unsigned short&>(h1);
    } else {
        __half l0 = __float2half_rn(w0 - __half2float(h0));
        __half l1 = __float2half_rn(w1 - __half2float(h1));
        u0 = reinterpret_cast<unsigned short&>(l0);
        u1 = reinterpret_cast<unsigned short&>(l1);
    }
    g_wAf32[idx] = ((uint32_t)u1 << 16) | (uint32_t)u0;
}

// ---------------- main kernel ----------------
__global__ void __launch_bounds__(NTHREADS, 2)
deform_kernel(const float* __restrict__ x,        // [B,C,H,W]
              const float* __restrict__ shape,    // [B,2,H,W]
              const float* __restrict__ w_offset, // [72][2]
              float* __restrict__ out)            // [B,COUT,H,W]
{
    extern __shared__ char smem[];
    const uint32_t smem_u32 = smem_to_u32(smem);
    float* ss0 = (float*)(smem + OFF_SS0);
    float* ss1 = (float*)(smem + OFF_SS1);
    float* swo = (float*)(smem + OFF_SWO);

    const int tid = threadIdx.x;
    const int wid = tid >> 5;
    const int lid = tid & 31;

    const int b   = blockIdx.x >> 9;
    const int rem = blockIdx.x & 511;
    const int h   = rem >> 2;
    const int w0  = (rem & 3) << 5;

    // ---- stage small tables ----
    if (tid < 32)                     ss0[tid]     = shape[(size_t)(b*2+0)*HW + h*WDIM + w0 + tid];
    else if (tid < 64)                ss1[tid-32]  = shape[(size_t)(b*2+1)*HW + h*WDIM + w0 + (tid-32)];
    else if (tid >= 64 && tid < 208)  swo[tid-64]  = w_offset[tid-64];
    __syncthreads();

    // ---- phase A: sample -> f16 into swizzled S [1152][32] (all 8 warps) ----
    for (int i = tid; i < 36 * TPX; i += NTHREADS) {
        int gk = i >> 5, px = i & 31;
        int g  = gk / 9, k = gk - g * 9;
        int ky = k / 3,  kx = k - ky * 3;
        float s0 = ss0[px], s1 = ss1[px];
        float offy = swo[gk*4 + 0] * s0 + swo[gk*4 + 1] * s1;
        float offx = swo[gk*4 + 2] * s0 + swo[gk*4 + 3] * s1;
        float py  = offy + (float)(ky - 1 + h);
        float pxf = offx + (float)(kx - 1 + w0 + px);
        float y0f = floorf(py), x0f = floorf(pxf);
        float fy = py - y0f, fx = pxf - x0f;
        int y0 = (int)y0f, x0 = (int)x0f;

        float aw[4]; int ai[4];
        #pragma unroll
        for (int t = 0; t < 4; t++) {
            int dy = t >> 1, dx = t & 1;
            int yi = y0 + dy, xi = x0 + dx;
            bool valid = (yi >= 0) && (yi < HDIM) && (xi >= 0) && (xi < WDIM);
            float wy = dy ? fy : 1.0f - fy;
            float wx = dx ? fx : 1.0f - fx;
            int yc = min(max(yi, 0), HDIM - 1);
            int xc = min(max(xi, 0), WDIM - 1);
            aw[t] = valid ? (wy * wx) : 0.0f;
            ai[t] = yc * WDIM + xc;
        }

        const float* xb = x + ((size_t)b * CIN + g * CG) * HW;
        const int r0 = (g * CG) * KTAPS + k;     // r for cg=0; stride 9 per cg
        #pragma unroll 4
        for (int cg = 0; cg < CG; cg++) {
            const float* xc = xb + (size_t)cg * HW;
            float v = aw[0]*xc[ai[0]] + aw[1]*xc[ai[1]] + aw[2]*xc[ai[2]] + aw[3]*xc[ai[3]];
            int r  = r0 + cg * KTAPS;
            *(__half*)(smem + SMEM_S_OFF + s_off(r, px)) = __float2half_rn(v);
        }
    }
    __syncthreads();

    // ---- phase B: 4 GEMM warps (o32 x n32 each); warps 4-7 retire ----
    if (wid >= 4) return;

    const int ot0   = wid << 1;          // otiles {ot0, ot0+1}
    const int bkrow = lid & 15;
    const int bsel  = lid >> 4;

    const uint4* gA = reinterpret_cast<const uint4*>(g_wAf32);

    float acc[2][4][4];
    #pragma unroll
    for (int a1 = 0; a1 < 2; a1++)
        #pragma unroll
        for (int a2 = 0; a2 < 4; a2++)
            #pragma unroll
            for (int a3 = 0; a3 < 4; a3++) acc[a1][a2][a3] = 0.0f;

    // A fragments: [ot][plane], 16B per lane per (step, otile, plane)
    uint4 curA[2][2];
    #pragma unroll
    for (int ot = 0; ot < 2; ot++)
        #pragma unroll
        for (int pl = 0; pl < 2; pl++)
            curA[ot][pl] = gA[(((0*8 + ot0 + ot)*2 + pl) << 5) + lid];

    for (int step = 0; step < NSTEP; step++) {
        // prefetch next step's A fragments (L2-resident stream)
        uint4 nxtA[2][2];
        if (step + 1 < NSTEP) {
            #pragma unroll
            for (int ot = 0; ot < 2; ot++)
                #pragma unroll
                for (int pl = 0; pl < 2; pl++)
                    nxtA[ot][pl] = gA[((((step+1)*8 + ot0 + ot)*2 + pl) << 5) + lid];
        }

        // B fragments: single f16 plane, two n16 halves
        const int k = (step << 4) + bkrow;
        uint32_t bf[2][4];
        #pragma unroll
        for (int half = 0; half < 2; half++) {
            int bnchk = (half << 1) + bsel;
            int boff  = (k << 6) + (((bnchk ^ ((k >> 1) & 3))) << 4);
            ldsm_x4_trans(bf[half], smem_u32 + SMEM_S_OFF + (uint32_t)boff);
        }

        // 16 MMAs: (ah + al) * b x 2 otiles x 4 n8 tiles
        #pragma unroll
        for (int ot = 0; ot < 2; ot++) {
            const uint32_t* ah = (const uint32_t*)&curA[ot][0];
            const uint32_t* al = (const uint32_t*)&curA[ot][1];
            #pragma unroll
            for (int half = 0; half < 2; half++) {
                mma_f16(acc[ot][half*2+0], ah, bf[half][0], bf[half][1]);
                mma_f16(acc[ot][half*2+1], ah, bf[half][2], bf[half][3]);
                mma_f16(acc[ot][half*2+0], al, bf[half][0], bf[half][1]);
                mma_f16(acc[ot][half*2+1], al, bf[half][2], bf[half][3]);
            }
        }

        #pragma unroll
        for (int ot = 0; ot < 2; ot++)
            #pragma unroll
            for (int pl = 0; pl < 2; pl++)
                curA[ot][pl] = nxtA[ot][pl];
    }

    // ---- epilogue: acc -> ReLU -> gmem ----
    const int g = lid >> 2, t = lid & 3;
    #pragma unroll
    for (int ot = 0; ot < 2; ot++) {
        #pragma unroll
        for (int j = 0; j < 4; j++) {
            int o  = (wid << 5) + (ot << 4) + g;
            int px = (j << 3) + (t << 1);
            float* op0 = out + (((size_t)b * COUT + o) << 14) + (h << 7) + w0 + px;
            float* op1 = op0 + ((size_t)8 << 14);   // row o+8
            float2 v0 = { fmaxf(acc[ot][j][0], 0.0f), fmaxf(acc[ot][j][1], 0.0f) };
            float2 v1 = { fmaxf(acc[ot][j][2], 0.0f), fmaxf(acc[ot][j][3], 0.0f) };
            *reinterpret_cast<float2*>(op0) = v0;
            *reinterpret_cast<float2*>(op1) = v1;
        }
    }
}

extern "C" void kernel_launch(void* const* d_in, const int* in_sizes, int n_in,
                              void* d_out, int out_size) {
    const float* x        = (const float*)d_in[0];
    const float* shape    = (const float*)d_in[1];
    const float* w_offset = (const float*)d_in[2];
    const float* w_deform = (const float*)d_in[3];
    float* out = (float*)d_out;

    cudaFuncSetAttribute(deform_kernel,
                         cudaFuncAttributeMaxDynamicSharedMemorySize, SMEM_BYTES);

    prep_wAf_kernel<<<(NSTEP * 8 * 2 * 32 * 4 + 255) / 256, 256>>>(w_deform);

    const int nblocks = BATCH * HDIM * (WDIM / TPX);   // 2048
    deform_kernel<<<nblocks, NTHREADS, SMEM_BYTES>>>(x, shape, w_offset, out);
}

// round 9
// speedup vs baseline: 2.1124x; 1.2849x over previous
#include <cuda_runtime.h>
#include <cuda_fp16.h>
#include <cstdint>

// ---------------- problem constants ----------------
#define BATCH   4
#define CIN     128
#define COUT    128
#define HDIM    128
#define WDIM    128
#define HW      (HDIM * WDIM)      // 16384
#define NGROUP  4
#define CG      32
#define KTAPS   9
#define RTOT    (CIN * KTAPS)      // 1152 = 72 * 16
#define NSTEP   72                 // k16 steps
#define HSTEP   36                 // steps per k-half
#define TPX     32                 // pixels (N) per block
#define NTHREADS 256

// ---------------- smem layout (bytes) ----------------
// S (samples, f16 single plane): [1152 k][64 B swizzled row] = 73728
// partial-accumulator buffer reuses S region after GEMM (128 x 33 floats = 16896 B)
// misc @ 73728: ss0(128), ss1(128), swo(576)
#define SMEM_S_OFF   0
#define SMEM_MISC    73728
#define OFF_SS0      (SMEM_MISC + 0)
#define OFF_SS1      (SMEM_MISC + 128)
#define OFF_SWO      (SMEM_MISC + 256)
#define SMEM_BYTES   (SMEM_MISC + 832)   // 74560
#define SACC_STRIDE  33                  // floats per o-row (pad kills bank conflicts)

// Weights pre-packed in m16n8k16 A-fragment order, single f16 plane:
// uint4 idx = (step*8 + otile)*32 + lane
__device__ __align__(16) uint32_t g_wAf32[NSTEP * 8 * 32 * 4];   // 294912 B

__device__ __forceinline__ uint32_t smem_to_u32(const void* p) {
    uint32_t a;
    asm("{ .reg .u64 t; cvta.to.shared.u64 t, %1; cvt.u32.u64 %0, t; }" : "=r"(a) : "l"(p));
    return a;
}

// S swizzle: row k is 64B (32 px f16), 4 x 16B chunks; chunk ^= (k>>1)&3 so
// ldmatrix's 8-row phases hit disjoint 16B groups.
__device__ __forceinline__ int s_off(int k, int px) {
    return (k << 6) + ((px & 7) << 1) + ((((px >> 3) ^ ((k >> 1) & 3))) << 4);
}

__device__ __forceinline__ void ldsm_x4_trans(uint32_t* r, uint32_t addr) {
    asm volatile("ldmatrix.sync.aligned.m8n8.x4.trans.shared.b16 {%0,%1,%2,%3}, [%4];"
                 : "=r"(r[0]), "=r"(r[1]), "=r"(r[2]), "=r"(r[3]) : "r"(addr));
}
__device__ __forceinline__ void mma_f16(float* c, const uint32_t* a, uint32_t b0, uint32_t b1) {
    asm volatile(
        "mma.sync.aligned.m16n8k16.row.col.f32.f16.f16.f32 "
        "{%0,%1,%2,%3}, {%4,%5,%6,%7}, {%8,%9}, {%0,%1,%2,%3};"
        : "+f"(c[0]), "+f"(c[1]), "+f"(c[2]), "+f"(c[3])
        : "r"(a[0]), "r"(a[1]), "r"(a[2]), "r"(a[3]), "r"(b0), "r"(b1));
}

// ---------------- prep: weights -> A-fragment layout, f16 ----------------
__global__ void prep_wAf_kernel(const float* __restrict__ wd) {
    int idx = blockIdx.x * 256 + threadIdx.x;       // b32 index
    if (idx >= NSTEP * 8 * 32 * 4) return;
    int q     = idx & 3;
    int lane  = (idx >> 2) & 31;
    int ot    = (idx >> 7) & 7;
    int step  = idx >> 10;
    int g = lane >> 2, t = lane & 3;
    int row = ot * 16 + g + ((q & 1) << 3);
    int col = step * 16 + t * 2 + ((q >> 1) << 3);
    __half h0 = __float2half_rn(wd[row * RTOT + col]);
    __half h1 = __float2half_rn(wd[row * RTOT + col + 1]);
    g_wAf32[idx] = ((uint32_t)reinterpret_cast<unsigned short&>(h1) << 16)
                 |  (uint32_t)reinterpret_cast<unsigned short&>(h0);
}

// ---------------- main kernel ----------------
__global__ void __launch_bounds__(NTHREADS, 2)
deform_kernel(const float* __restrict__ x,        // [B,C,H,W]
              const float* __restrict__ shape,    // [B,2,H,W]
              const float* __restrict__ w_offset, // [72][2]
              float* __restrict__ out)            // [B,COUT,H,W]
{
    extern __shared__ char smem[];
    const uint32_t smem_u32 = smem_to_u32(smem);
    float* ss0  = (float*)(smem + OFF_SS0);
    float* ss1  = (float*)(smem + OFF_SS1);
    float* swo  = (float*)(smem + OFF_SWO);
    float* sacc = (float*)(smem + SMEM_S_OFF);   // alias of S, used after GEMM

    const int tid = threadIdx.x;
    const int wid = tid >> 5;
    const int lid = tid & 31;

    const int b   = blockIdx.x >> 9;
    const int rem = blockIdx.x & 511;
    const int h   = rem >> 2;
    const int w0  = (rem & 3) << 5;

    // ---- stage small tables ----
    if (tid < 32)                     ss0[tid]     = shape[(size_t)(b*2+0)*HW + h*WDIM + w0 + tid];
    else if (tid < 64)                ss1[tid-32]  = shape[(size_t)(b*2+1)*HW + h*WDIM + w0 + (tid-32)];
    else if (tid >= 64 && tid < 208)  swo[tid-64]  = w_offset[tid-64];
    __syncthreads();

    // ---- phase A: sample -> f16 into swizzled S [1152][32] (all 8 warps) ----
    for (int i = tid; i < 36 * TPX; i += NTHREADS) {
        int gk = i >> 5, px = i & 31;
        int g  = gk / 9, k = gk - g * 9;
        int ky = k / 3,  kx = k - ky * 3;
        float s0 = ss0[px], s1 = ss1[px];
        float offy = swo[gk*4 + 0] * s0 + swo[gk*4 + 1] * s1;
        float offx = swo[gk*4 + 2] * s0 + swo[gk*4 + 3] * s1;
        float py  = offy + (float)(ky - 1 + h);
        float pxf = offx + (float)(kx - 1 + w0 + px);
        float y0f = floorf(py), x0f = floorf(pxf);
        float fy = py - y0f, fx = pxf - x0f;
        int y0 = (int)y0f, x0 = (int)x0f;

        float aw[4]; int ai[4];
        #pragma unroll
        for (int t = 0; t < 4; t++) {
            int dy = t >> 1, dx = t & 1;
            int yi = y0 + dy, xi = x0 + dx;
            bool valid = (yi >= 0) && (yi < HDIM) && (xi >= 0) && (xi < WDIM);
            float wy = dy ? fy : 1.0f - fy;
            float wx = dx ? fx : 1.0f - fx;
            int yc = min(max(yi, 0), HDIM - 1);
            int xc = min(max(xi, 0), WDIM - 1);
            aw[t] = valid ? (wy * wx) : 0.0f;
            ai[t] = yc * WDIM + xc;
        }

        const float* xb = x + ((size_t)b * CIN + g * CG) * HW;
        const int r0 = (g * CG) * KTAPS + k;     // r for cg=0; stride 9 per cg
        #pragma unroll 4
        for (int cg = 0; cg < CG; cg++) {
            const float* xc = xb + (size_t)cg * HW;
            float v = aw[0]*xc[ai[0]] + aw[1]*xc[ai[1]] + aw[2]*xc[ai[2]] + aw[3]*xc[ai[3]];
            int r  = r0 + cg * KTAPS;
            *(__half*)(smem + SMEM_S_OFF + s_off(r, px)) = __float2half_rn(v);
        }
    }
    __syncthreads();

    // ---- phase B: 8 warps, k-split GEMM ----
    // warp w: k-half kw = w>>2 (steps kw*36 .. +36), otile pair cw = w&3
    const int kw    = wid >> 2;
    const int cw    = wid & 3;
    const int ot0   = cw << 1;
    const int bkrow = lid & 15;
    const int bsel  = lid >> 4;

    const uint4* gA = reinterpret_cast<const uint4*>(g_wAf32);

    float acc[2][4][4];
    #pragma unroll
    for (int a1 = 0; a1 < 2; a1++)
        #pragma unroll
        for (int a2 = 0; a2 < 4; a2++)
            #pragma unroll
            for (int a3 = 0; a3 < 4; a3++) acc[a1][a2][a3] = 0.0f;

    const int step0 = kw * HSTEP;
    uint4 curA[2];
    #pragma unroll
    for (int ot = 0; ot < 2; ot++)
        curA[ot] = gA[((step0*8 + ot0 + ot) << 5) + lid];

    for (int s = 0; s < HSTEP; s++) {
        const int step = step0 + s;
        // prefetch next step's A fragments (L2-resident stream)
        uint4 nxtA[2];
        if (s + 1 < HSTEP) {
            #pragma unroll
            for (int ot = 0; ot < 2; ot++)
                nxtA[ot] = gA[(((step+1)*8 + ot0 + ot) << 5) + lid];
        }

        // B fragments: two n16 halves
        const int k = (step << 4) + bkrow;
        uint32_t bf[2][4];
        #pragma unroll
        for (int half = 0; half < 2; half++) {
            int bnchk = (half << 1) + bsel;
            int boff  = (k << 6) + (((bnchk ^ ((k >> 1) & 3))) << 4);
            ldsm_x4_trans(bf[half], smem_u32 + SMEM_S_OFF + (uint32_t)boff);
        }

        // 8 MMAs: a * b x 2 otiles x 4 n8 tiles
        #pragma unroll
        for (int ot = 0; ot < 2; ot++) {
            const uint32_t* a = (const uint32_t*)&curA[ot];
            #pragma unroll
            for (int half = 0; half < 2; half++) {
                mma_f16(acc[ot][half*2+0], a, bf[half][0], bf[half][1]);
                mma_f16(acc[ot][half*2+1], a, bf[half][2], bf[half][3]);
            }
        }

        #pragma unroll
        for (int ot = 0; ot < 2; ot++) curA[ot] = nxtA[ot];
    }
    __syncthreads();    // all LDSM from S done; S now reusable as sacc

    // ---- reduction: warps 4-7 dump partials; warps 0-3 add + ReLU + store ----
    const int g = lid >> 2, t = lid & 3;
    if (kw == 1) {
        #pragma unroll
        for (int ot = 0; ot < 2; ot++) {
            #pragma unroll
            for (int j = 0; j < 4; j++) {
                int o  = (cw << 5) + (ot << 4) + g;
                int px = (j << 3) + (t << 1);
                sacc[ o      * SACC_STRIDE + px    ] = acc[ot][j][0];
                sacc[ o      * SACC_STRIDE + px + 1] = acc[ot][j][1];
                sacc[(o + 8) * SACC_STRIDE + px    ] = acc[ot][j][2];
                sacc[(o + 8) * SACC_STRIDE + px + 1] = acc[ot][j][3];
            }
        }
    }
    __syncthreads();
    if (kw == 0) {
        #pragma unroll
        for (int ot = 0; ot < 2; ot++) {
            #pragma unroll
            for (int j = 0; j < 4; j++) {
                int o  = (cw << 5) + (ot << 4) + g;
                int px = (j << 3) + (t << 1);
                float* op0 = out + (((size_t)b * COUT + o) << 14) + (h << 7) + w0 + px;
                float* op1 = op0 + ((size_t)8 << 14);   // row o+8
                float2 v0, v1;
                v0.x = fmaxf(acc[ot][j][0] + sacc[ o      * SACC_STRIDE + px    ], 0.0f);
                v0.y = fmaxf(acc[ot][j][1] + sacc[ o      * SACC_STRIDE + px + 1], 0.0f);
                v1.x = fmaxf(acc[ot][j][2] + sacc[(o + 8) * SACC_STRIDE + px    ], 0.0f);
                v1.y = fmaxf(acc[ot][j][3] + sacc[(o + 8) * SACC_STRIDE + px + 1], 0.0f);
                *reinterpret_cast<float2*>(op0) = v0;
                *reinterpret_cast<float2*>(op1) = v1;
            }
        }
    }
}

extern "C" void kernel_launch(void* const* d_in, const int* in_sizes, int n_in,
                              void* d_out, int out_size) {
    const float* x        = (const float*)d_in[0];
    const float* shape    = (const float*)d_in[1];
    const float* w_offset = (const float*)d_in[2];
    const float* w_deform = (const float*)d_in[3];
    float* out = (float*)d_out;

    cudaFuncSetAttribute(deform_kernel,
                         cudaFuncAttributeMaxDynamicSharedMemorySize, SMEM_BYTES);

    prep_wAf_kernel<<<(NSTEP * 8 * 32 * 4 + 255) / 256, 256>>>(w_deform);

    const int nblocks = BATCH * HDIM * (WDIM / TPX);   // 2048
    deform_kernel<<<nblocks, NTHREADS, SMEM_BYTES>>>(x, shape, w_offset, out);
}

// round 10
// speedup vs baseline: 2.1652x; 1.0250x over previous
#include <cuda_runtime.h>
#include <cuda_fp16.h>
#include <cstdint>

// ---------------- problem constants ----------------
#define BATCH   4
#define CIN     128
#define COUT    128
#define HDIM    128
#define WDIM    128
#define HW      (HDIM * WDIM)      // 16384
#define NGROUP  4
#define CG      32
#define KTAPS   9
#define RTOT    (CIN * KTAPS)      // 1152 = 72 * 16
#define NSTEP   72                 // k16 steps
#define TPX     32                 // pixels (N) per block
#define NTHREADS 256

// ---------------- smem layout (bytes) ----------------
// S (samples, f16 single plane): [1152 k][64 B swizzled row] = 73728
// misc @ 73728: ss0(128), ss1(128), swo(576)
#define SMEM_S_OFF   0
#define SMEM_MISC    73728
#define OFF_SS0      (SMEM_MISC + 0)
#define OFF_SS1      (SMEM_MISC + 128)
#define OFF_SWO      (SMEM_MISC + 256)
#define SMEM_BYTES   (SMEM_MISC + 832)   // 74560  (x3 CTAs = 223,680 <= 227KB)

// Weights pre-packed in m16n8k16 A-fragment order, single f16 plane:
// uint4 idx = (step*8 + otile)*32 + lane
__device__ __align__(16) uint32_t g_wAf32[NSTEP * 8 * 32 * 4];   // 294912 B

__device__ __forceinline__ uint32_t smem_to_u32(const void* p) {
    uint32_t a;
    asm("{ .reg .u64 t; cvta.to.shared.u64 t, %1; cvt.u32.u64 %0, t; }" : "=r"(a) : "l"(p));
    return a;
}

// S swizzle: row k is 64B (32 px f16), 4 x 16B chunks; chunk ^= (k>>1)&3 so
// ldmatrix's 8-row phases hit disjoint 16B groups.
__device__ __forceinline__ int s_off(int k, int px) {
    return (k << 6) + ((px & 7) << 1) + ((((px >> 3) ^ ((k >> 1) & 3))) << 4);
}

__device__ __forceinline__ void ldsm_x4_trans(uint32_t* r, uint32_t addr) {
    asm volatile("ldmatrix.sync.aligned.m8n8.x4.trans.shared.b16 {%0,%1,%2,%3}, [%4];"
                 : "=r"(r[0]), "=r"(r[1]), "=r"(r[2]), "=r"(r[3]) : "r"(addr));
}
__device__ __forceinline__ void mma_f16(float* c, const uint32_t* a, uint32_t b0, uint32_t b1) {
    asm volatile(
        "mma.sync.aligned.m16n8k16.row.col.f32.f16.f16.f32 "
        "{%0,%1,%2,%3}, {%4,%5,%6,%7}, {%8,%9}, {%0,%1,%2,%3};"
        : "+f"(c[0]), "+f"(c[1]), "+f"(c[2]), "+f"(c[3])
        : "r"(a[0]), "r"(a[1]), "r"(a[2]), "r"(a[3]), "r"(b0), "r"(b1));
}

// ---------------- prep: weights -> A-fragment layout, f16 ----------------
__global__ void prep_wAf_kernel(const float* __restrict__ wd) {
    int idx = blockIdx.x * 256 + threadIdx.x;       // b32 index
    if (idx >= NSTEP * 8 * 32 * 4) return;
    int q     = idx & 3;
    int lane  = (idx >> 2) & 31;
    int ot    = (idx >> 7) & 7;
    int step  = idx >> 10;
    int g = lane >> 2, t = lane & 3;
    int row = ot * 16 + g + ((q & 1) << 3);
    int col = step * 16 + t * 2 + ((q >> 1) << 3);
    __half h0 = __float2half_rn(wd[row * RTOT + col]);
    __half h1 = __float2half_rn(wd[row * RTOT + col + 1]);
    g_wAf32[idx] = ((uint32_t)reinterpret_cast<unsigned short&>(h1) << 16)
                 |  (uint32_t)reinterpret_cast<unsigned short&>(h0);
}

// ---------------- main kernel ----------------
__global__ void __launch_bounds__(NTHREADS, 3)
deform_kernel(const float* __restrict__ x,        // [B,C,H,W]
              const float* __restrict__ shape,    // [B,2,H,W]
              const float* __restrict__ w_offset, // [72][2]
              float* __restrict__ out)            // [B,COUT,H,W]
{
    extern __shared__ char smem[];
    const uint32_t smem_u32 = smem_to_u32(smem);
    float* ss0 = (float*)(smem + OFF_SS0);
    float* ss1 = (float*)(smem + OFF_SS1);
    float* swo = (float*)(smem + OFF_SWO);

    const int tid = threadIdx.x;
    const int wid = tid >> 5;
    const int lid = tid & 31;

    const int b   = blockIdx.x >> 9;
    const int rem = blockIdx.x & 511;
    const int h   = rem >> 2;
    const int w0  = (rem & 3) << 5;

    // ---- stage small tables ----
    if (tid < 32)                     ss0[tid]     = shape[(size_t)(b*2+0)*HW + h*WDIM + w0 + tid];
    else if (tid < 64)                ss1[tid-32]  = shape[(size_t)(b*2+1)*HW + h*WDIM + w0 + (tid-32)];
    else if (tid >= 64 && tid < 208)  swo[tid-64]  = w_offset[tid-64];
    __syncthreads();

    // ---- phase A: sample -> f16 into swizzled S [1152][32] (all 8 warps) ----
    for (int i = tid; i < 36 * TPX; i += NTHREADS) {
        int gk = i >> 5, px = i & 31;
        int g  = gk / 9, k = gk - g * 9;
        int ky = k / 3,  kx = k - ky * 3;
        float s0 = ss0[px], s1 = ss1[px];
        float offy = swo[gk*4 + 0] * s0 + swo[gk*4 + 1] * s1;
        float offx = swo[gk*4 + 2] * s0 + swo[gk*4 + 3] * s1;
        float py  = offy + (float)(ky - 1 + h);
        float pxf = offx + (float)(kx - 1 + w0 + px);
        float y0f = floorf(py), x0f = floorf(pxf);
        float fy = py - y0f, fx = pxf - x0f;
        int y0 = (int)y0f, x0 = (int)x0f;

        float aw[4]; int ai[4];
        #pragma unroll
        for (int t = 0; t < 4; t++) {
            int dy = t >> 1, dx = t & 1;
            int yi = y0 + dy, xi = x0 + dx;
            bool valid = (yi >= 0) && (yi < HDIM) && (xi >= 0) && (xi < WDIM);
            float wy = dy ? fy : 1.0f - fy;
            float wx = dx ? fx : 1.0f - fx;
            int yc = min(max(yi, 0), HDIM - 1);
            int xc = min(max(xi, 0), WDIM - 1);
            aw[t] = valid ? (wy * wx) : 0.0f;
            ai[t] = yc * WDIM + xc;
        }

        const float* xb = x + ((size_t)b * CIN + g * CG) * HW;
        const int r0 = (g * CG) * KTAPS + k;     // r for cg=0; stride 9 per cg
        #pragma unroll 4
        for (int cg = 0; cg < CG; cg++) {
            const float* xc = xb + (size_t)cg * HW;
            float v = aw[0]*xc[ai[0]] + aw[1]*xc[ai[1]] + aw[2]*xc[ai[2]] + aw[3]*xc[ai[3]];
            int r  = r0 + cg * KTAPS;
            *(__half*)(smem + SMEM_S_OFF + s_off(r, px)) = __float2half_rn(v);
        }
    }
    __syncthreads();

    // ---- phase B: 8 warps, each o16 x n32 over full k ----
    const int ot    = wid;               // o = wid*16 .. +15
    const int bkrow = lid & 15;
    const int bsel  = lid >> 4;

    const uint4* gA = reinterpret_cast<const uint4*>(g_wAf32);

    float acc[4][4];
    #pragma unroll
    for (int a2 = 0; a2 < 4; a2++)
        #pragma unroll
        for (int a3 = 0; a3 < 4; a3++) acc[a2][a3] = 0.0f;

    uint4 curA = gA[((0*8 + ot) << 5) + lid];

    for (int step = 0; step < NSTEP; step++) {
        // prefetch next step's A fragment (L2-resident stream)
        uint4 nxtA;
        if (step + 1 < NSTEP)
            nxtA = gA[(((step+1)*8 + ot) << 5) + lid];

        // B fragments: two n16 halves
        const int k = (step << 4) + bkrow;
        uint32_t bf[2][4];
        #pragma unroll
        for (int half = 0; half < 2; half++) {
            int bnchk = (half << 1) + bsel;
            int boff  = (k << 6) + (((bnchk ^ ((k >> 1) & 3))) << 4);
            ldsm_x4_trans(bf[half], smem_u32 + SMEM_S_OFF + (uint32_t)boff);
        }

        // 4 MMAs: a * b x 4 n8 tiles
        const uint32_t* a = (const uint32_t*)&curA;
        mma_f16(acc[0], a, bf[0][0], bf[0][1]);
        mma_f16(acc[1], a, bf[0][2], bf[0][3]);
        mma_f16(acc[2], a, bf[1][0], bf[1][1]);
        mma_f16(acc[3], a, bf[1][2], bf[1][3]);

        curA = nxtA;
    }

    // ---- epilogue: acc -> ReLU -> gmem ----
    const int g = lid >> 2, t = lid & 3;
    #pragma unroll
    for (int j = 0; j < 4; j++) {
        int o  = (wid << 4) + g;
        int px = (j << 3) + (t << 1);
        float* op0 = out + (((size_t)b * COUT + o) << 14) + (h << 7) + w0 + px;
        float* op1 = op0 + ((size_t)8 << 14);   // row o+8
        float2 v0 = { fmaxf(acc[j][0], 0.0f), fmaxf(acc[j][1], 0.0f) };
        float2 v1 = { fmaxf(acc[j][2], 0.0f), fmaxf(acc[j][3], 0.0f) };
        *reinterpret_cast<float2*>(op0) = v0;
        *reinterpret_cast<float2*>(op1) = v1;
    }
}

extern "C" void kernel_launch(void* const* d_in, const int* in_sizes, int n_in,
                              void* d_out, int out_size) {
    const float* x        = (const float*)d_in[0];
    const float* shape    = (const float*)d_in[1];
    const float* w_offset = (const float*)d_in[2];
    const float* w_deform = (const float*)d_in[3];
    float* out = (float*)d_out;

    cudaFuncSetAttribute(deform_kernel,
                         cudaFuncAttributeMaxDynamicSharedMemorySize, SMEM_BYTES);

    prep_wAf_kernel<<<(NSTEP * 8 * 32 * 4 + 255) / 256, 256>>>(w_deform);

    const int nblocks = BATCH * HDIM * (WDIM / TPX);   // 2048
    deform_kernel<<<nblocks, NTHREADS, SMEM_BYTES>>>(x, shape, w_offset, out);
}